// round 14
// baseline (speedup 1.0000x reference)
#include <cuda_runtime.h>
#include <cstdint>

// GTConvAE — fused persistent kernel, R14 = R13 + combine-G0 smem prefetch in
// barrier windows. Kronecker identity: S^k x[tau] = sum_{a,b<3} c_k[a][b] *
// Sg^b x[(tau-a) mod t]. Layer = two GEMMs (G1=Sg@act, G2=Sg2@act) + 9-term
// combine with folded filters. Encoder fuses maxpool+relu; decoder exploits
// zero-stuffed upsampling. Split arrive/wait barriers; windows hide Hs builds,
// A-band prefetch, and now combine-G0 staging (G0 is stable one barrier before
// its combine consumes it).

#define NN  192
#define TT  32
#define NB  128
#define KS  196

// ---------------- scratch --------------------------------------------------------
__device__ float g_Sg2 [NN * NN];
__device__ float g_G1  [256 * NN];
__device__ float g_G2  [256 * NN];
__device__ float g_actA[256 * NN];
__device__ float g_actB[256 * NN];
__device__ unsigned g_cnt = 0;
__device__ unsigned g_gen = 0;

// ---------------- split grid barrier ---------------------------------------------
__device__ __forceinline__ unsigned bar_arrive()
{
    unsigned gen;
    asm volatile("ld.relaxed.gpu.u32 %0, [%1];"
                 : "=r"(gen) : "l"(&g_gen) : "memory");
    unsigned prev;
    asm volatile("atom.release.gpu.add.u32 %0, [%1], %2;"
                 : "=r"(prev) : "l"(&g_cnt), "r"(1u) : "memory");
    if (prev == NB - 1) {
        asm volatile("st.relaxed.gpu.u32 [%0], %1;"
                     :: "l"(&g_cnt), "r"(0u) : "memory");
        asm volatile("st.release.gpu.u32 [%0], %1;"
                     :: "l"(&g_gen), "r"(gen + 1u) : "memory");
    }
    return gen + 1;
}
__device__ __forceinline__ void bar_wait(unsigned target)
{
    unsigned cur;
    do {
        asm volatile("ld.acquire.gpu.u32 %0, [%1];"
                     : "=r"(cur) : "l"(&g_gen) : "memory");
    } while ((int)(cur - target) < 0);
}

// ---------------- cp.async helpers ----------------------------------------------
__device__ __forceinline__ void cp16(float* dst, const float* src, bool cg)
{
    uint32_t d = (uint32_t)__cvta_generic_to_shared(dst);
    if (cg)
        asm volatile("cp.async.cg.shared.global [%0], [%1], 16;" :: "r"(d), "l"(src));
    else
        asm volatile("cp.async.ca.shared.global [%0], [%1], 16;" :: "r"(d), "l"(src));
}
__device__ __forceinline__ void cp_wait_all()
{
    asm volatile("cp.async.wait_all;" ::: "memory");
}

// ---------------- tile loaders (128 threads) -------------------------------------
__device__ __forceinline__ void loadA24(const float* __restrict__ A, int m0,
                                        bool cg, float* As)
{
    #pragma unroll
    for (int r = 0; r < 9; r++) {
        int op = threadIdx.x + 128 * r;          // 0..1151
        int ml = op / 48, kq = op - ml * 48;
        cp16(&As[ml * KS + 4 * kq], &A[(m0 + ml) * NN + 4 * kq], cg);
    }
}
// 16 rows (j0..j0+15) of a [rows x NN] matrix -> buf[j][k] at stride KS
__device__ __forceinline__ void loadB16(const float* __restrict__ Bg, int j0,
                                        float* Bsb)
{
    #pragma unroll
    for (int r = 0; r < 6; r++) {
        int op = threadIdx.x + 128 * r;          // 0..767
        int jl = op / 48, kq = op - jl * 48;
        cp16(&Bsb[jl * KS + 4 * kq], &Bg[(j0 + jl) * NN + 4 * kq], true);
    }
}

// ---------------- compute one 24m x 16j tile (128 threads) -----------------------
template <bool CROW>
__device__ __forceinline__ void tile_compute(const float* __restrict__ As,
                                             const float* __restrict__ Bsb,
                                             float* __restrict__ C, int m0, int j0)
{
    const int tid = threadIdx.x;
    const int tx = tid & 15, ty = tid >> 4;
    float acc0 = 0.f, acc1 = 0.f, acc2 = 0.f;
    const float* bp  = Bsb + tx * KS;
    const float* ap0 = As + ty * KS;
    const float* ap1 = ap0 + 8 * KS;
    const float* ap2 = ap0 + 16 * KS;
    #pragma unroll 8
    for (int k = 0; k < NN; k += 4) {
        float4 b  = *(const float4*)(bp + k);
        float4 a0 = *(const float4*)(ap0 + k);
        float4 a1 = *(const float4*)(ap1 + k);
        float4 a2 = *(const float4*)(ap2 + k);
        acc0 += a0.x * b.x; acc0 += a0.y * b.y; acc0 += a0.z * b.z; acc0 += a0.w * b.w;
        acc1 += a1.x * b.x; acc1 += a1.y * b.y; acc1 += a1.z * b.z; acc1 += a1.w * b.w;
        acc2 += a2.x * b.x; acc2 += a2.y * b.y; acc2 += a2.z * b.z; acc2 += a2.w * b.w;
    }
    const int j = j0 + tx;
    if (CROW) {
        C[(m0 + ty     ) * NN + j] = acc0;
        C[(m0 + ty +  8) * NN + j] = acc1;
        C[(m0 + ty + 16) * NN + j] = acc2;
    } else {
        C[j * NN + m0 + ty     ] = acc0;
        C[j * NN + m0 + ty +  8] = acc1;
        C[j * NN + m0 + ty + 16] = acc2;
    }
}

// ---------------- big GEMM stage: 2 j-tiles, double-buffered B -------------------
template <bool LOADA>
__device__ void big_stage(const float* __restrict__ A, bool acg,
                          const float* __restrict__ Bact,
                          float* __restrict__ C, int m0, int j0,
                          float* As, float* Bs0, float* Bs1)
{
    if (LOADA) loadA24(A, m0, acg, As);
    loadB16(Bact, j0, Bs0);
    cp_wait_all(); __syncthreads();
    loadB16(Bact, j0 + 16, Bs1);
    tile_compute<false>(As, Bs0, C, m0, j0);
    cp_wait_all(); __syncthreads();
    tile_compute<false>(As, Bs1, C, m0, j0 + 16);
}

// ---------------- S0 tile: B from column-slices (Sg or X) ------------------------
template <int BMODE, bool CROW>
__device__ void s0_tile(const float* __restrict__ A, const float* __restrict__ Bg,
                        int j0, float* __restrict__ C, int m0,
                        float* As, float* Bs0)
{
    loadA24(A, m0, false, As);
    const int tid = threadIdx.x;
    #pragma unroll
    for (int r = 0; r < 24; r++) {
        int idx = tid + 128 * r;                 // 0..3071
        int jl = idx & 15, kk = idx >> 4;
        Bs0[jl * KS + kk] = (BMODE == 1) ? Bg[kk * NN + j0 + jl]
                                         : Bg[kk * TT + j0 + jl];
    }
    cp_wait_all(); __syncthreads();
    tile_compute<CROW>(As, Bs0, C, m0, j0);
}

// ---------------- folded filters -------------------------------------------------
__device__ __forceinline__ float fold_H(const float* __restrict__ h3,
                                        const float sv[4], int a, int b)
{
    float c0 = (a == 0 && b == 0) ? 1.f : 0.f;
    float c1 = (a < 2 && b < 2) ? sv[a * 2 + b] : 0.f;
    float c2 = 0.f;
    #pragma unroll
    for (int a1 = 0; a1 < 2; a1++)
        #pragma unroll
        for (int b1 = 0; b1 < 2; b1++) {
            int a2 = a - a1, b2 = b - b1;
            if (a2 >= 0 && a2 < 2 && b2 >= 0 && b2 < 2)
                c2 += sv[a1 * 2 + b1] * sv[a2 * 2 + b2];
        }
    return h3[0] * c0 + h3[1] * c1 + h3[2] * c2;
}

__device__ __forceinline__ void build_Hs(float* Hs, const float* __restrict__ h,
                                         const float sv[4], int CI, int OT, int ob)
{
    for (int idx = threadIdx.x; idx < CI * 9 * OT; idx += 128) {
        int oo = idx % OT;
        int tmp = idx / OT;
        int b = tmp % 3, a = (tmp / 3) % 3, i = tmp / 9;
        Hs[idx] = fold_H(&h[((ob + oo) * CI + i) * 3], sv, a, b);
    }
}

// ---------------- e2 combine body: G0 of tt=0/1 pre-staged in smem ---------------
__device__ void combine_e2_body(const float* __restrict__ G0,
                                const float* __restrict__ G1,
                                const float* __restrict__ G2,
                                float* __restrict__ out, int tp, int ob,
                                const float* Hs, const float* S0, const float* S1)
{
    const int tid = threadIdx.x;
    if (tid < 96) {
        const int n2 = 2 * tid;
        float2 acc0[2], acc1[2];
        #pragma unroll
        for (int o = 0; o < 2; o++) {
            acc0[o] = make_float2(0.f, 0.f); acc1[o] = make_float2(0.f, 0.f);
        }
        #pragma unroll
        for (int tt = 0; tt < 4; tt++) {
            int src = (2 * tp - 2 + tt + 16) & 15;
            #pragma unroll
            for (int i = 0; i < 16; i++) {
                float2 v0;
                if      (tt == 0) v0 = *(const float2*)&S0[i * KS + n2];
                else if (tt == 1) v0 = *(const float2*)&S1[i * KS + n2];
                else v0 = __ldcg((const float2*)&G0[(src * 16 + i) * NN + n2]);
                float2 v1 = __ldcg((const float2*)&G1[(src * 16 + i) * NN + n2]);
                float2 v2 = __ldcg((const float2*)&G2[(src * 16 + i) * NN + n2]);
                if (tt <= 2) {
                    const float* Hp = &Hs[(i * 3 + (2 - tt)) * 6];
                    #pragma unroll
                    for (int o = 0; o < 2; o++) {
                        float h0 = Hp[o], h1 = Hp[2 + o], h2 = Hp[4 + o];
                        acc0[o].x += h0 * v0.x + h1 * v1.x + h2 * v2.x;
                        acc0[o].y += h0 * v0.y + h1 * v1.y + h2 * v2.y;
                    }
                }
                if (tt >= 1) {
                    const float* Hp = &Hs[(i * 3 + (3 - tt)) * 6];
                    #pragma unroll
                    for (int o = 0; o < 2; o++) {
                        float h0 = Hp[o], h1 = Hp[2 + o], h2 = Hp[4 + o];
                        acc1[o].x += h0 * v0.x + h1 * v1.x + h2 * v2.x;
                        acc1[o].y += h0 * v0.y + h1 * v1.y + h2 * v2.y;
                    }
                }
            }
        }
        #pragma unroll
        for (int o = 0; o < 2; o++) {
            float2 r;
            r.x = fmaxf(fmaxf(acc0[o].x, acc1[o].x), 0.f);
            r.y = fmaxf(fmaxf(acc0[o].y, acc1[o].y), 0.f);
            *(float2*)&out[(tp * 32 + ob + o) * NN + n2] = r;
        }
    }
}

// ---------------- d1 combine body: G0 rows of tl0 pre-staged ---------------------
__device__ void combine_d1_body(const float* __restrict__ G0,
                                const float* __restrict__ G1,
                                const float* __restrict__ G2,
                                float* __restrict__ out, int tau, int ob,
                                const float* Hs, int tl0,
                                const float* S0, const float* S1)
{
    const int tid = threadIdx.x;
    if (tid < 96) {
        const int n2 = 2 * tid;
        float2 acc[2] = { {0.f, 0.f}, {0.f, 0.f} };
        #pragma unroll
        for (int a = 0; a < 3; a++) {
            int src = tau - a; if (src < 0) src += 16;
            if (src & 1) continue;
            int tl = src >> 1;
            bool insm = (tl == tl0);
            #pragma unroll 16
            for (int i = 0; i < 32; i++) {
                float2 v0;
                if (insm) v0 = (i < 16) ? *(const float2*)&S0[i * KS + n2]
                                        : *(const float2*)&S1[(i - 16) * KS + n2];
                else      v0 = __ldcg((const float2*)&G0[(tl * 32 + i) * NN + n2]);
                float2 v1 = __ldcg((const float2*)&G1[(tl * 32 + i) * NN + n2]);
                float2 v2 = __ldcg((const float2*)&G2[(tl * 32 + i) * NN + n2]);
                const float* Hp = &Hs[(i * 3 + a) * 6];
                #pragma unroll
                for (int o = 0; o < 2; o++) {
                    float h0 = Hp[o], h1 = Hp[2 + o], h2 = Hp[4 + o];
                    acc[o].x += h0 * v0.x + h1 * v1.x + h2 * v2.x;
                    acc[o].y += h0 * v0.y + h1 * v1.y + h2 * v2.y;
                }
            }
        }
        #pragma unroll
        for (int o = 0; o < 2; o++) {
            float2 r;
            r.x = fmaxf(acc[o].x, 0.f);
            r.y = fmaxf(acc[o].y, 0.f);
            *(float2*)&out[(tau * 16 + ob + o) * NN + n2] = r;
        }
    }
}

// ---------------- persistent mega-kernel ----------------------------------------
__global__ __launch_bounds__(128, 1) void mega(
    const float* __restrict__ X,    const float* __restrict__ Sg,
    const float* __restrict__ s,    const float* __restrict__ h_e1,
    const float* __restrict__ h_e2, const float* __restrict__ h_d1,
    const float* __restrict__ h_d2, float* __restrict__ out)
{
    __shared__ float As[24 * KS];    // persistent A band
    __shared__ float Bs0[16 * KS];
    __shared__ float Bs1[16 * KS];
    __shared__ float Hs[576];
    __shared__ float G2s[96];

    const int bid = blockIdx.x;
    const int tid = threadIdx.x;

    const int mat = bid >> 6;                 // 0: Sg, 1: Sg2
    const int sub = bid & 63;
    const int gm0 = (sub >> 3) * 24;
    const int gj0 = (sub & 7) * 32;

    const float sv[4] = { s[0], s[1], s[2], s[3] };
    unsigned bg = 0;

    // ======== S0: Sg2 (96 tiles) + P = Sg@X (16 tiles) ========
    if (bid < 96) {
        int mb = bid / 12, jt = bid % 12;
        s0_tile<1, true>(Sg, Sg, jt * 16, g_Sg2, mb * 24, As, Bs0);
    } else if (bid < 112) {
        int b2 = bid - 96;
        int mb = b2 >> 1, jt = b2 & 1;
        s0_tile<2, false>(Sg, X, jt * 16, g_G1, mb * 24, As, Bs0);
    }
    // --- barrier 1 window: e1 Hs + S1' mini-GEMM A band (Sg rows, input) ---
    __syncthreads();
    if (tid == 0) bg = bar_arrive();
    {
        const int nb = bid >> 4;
        loadA24(Sg, nb * 24, false, As);
        for (int idx = tid; idx < 144; idx += 128) {
            int o = idx & 15, ab = idx >> 4;
            Hs[idx] = fold_H(&h_e1[o * 3], sv, ab / 3, ab % 3);
        }
    }
    if (tid == 0) bar_wait(bg);
    __syncthreads();

    // ======== S1': e1 combine with fused mini-GEMM for G2 ========
    {
        const int tp = bid & 15, nb = bid >> 4;
        const int n0 = nb * 24;
        #pragma unroll
        for (int r = 0; r < 2; r++) {
            int op = tid + 128 * r;
            if (op < 192) {
                int ttl = op / 48, kq = op - ttl * 48;
                int src = (2 * tp - 2 + ttl + TT) & (TT - 1);
                cp16(&Bs0[ttl * KS + 4 * kq], &g_G1[src * NN + 4 * kq], true);
            }
        }
        cp_wait_all(); __syncthreads();
        if (tid < 96) {
            int nl = tid % 24, st = tid / 24;
            float acc = 0.f;
            const float* ap = As + nl * KS;
            const float* bp = Bs0 + st * KS;
            #pragma unroll 12
            for (int k = 0; k < NN; k += 4) {
                float4 a = *(const float4*)(ap + k);
                float4 b = *(const float4*)(bp + k);
                acc += a.x * b.x; acc += a.y * b.y; acc += a.z * b.z; acc += a.w * b.w;
            }
            G2s[st * 24 + nl] = acc;
        }
        __syncthreads();
        if (tid < 96) {
            int nl = tid % 24, og = tid / 24;
            int n = n0 + nl;
            float acc0[4] = {0.f, 0.f, 0.f, 0.f};
            float acc1[4] = {0.f, 0.f, 0.f, 0.f};
            #pragma unroll
            for (int ttl = 0; ttl < 4; ttl++) {
                int src = (2 * tp - 2 + ttl + TT) & (TT - 1);
                float v0 = X[n * TT + src];
                float v1 = Bs0[ttl * KS + n];
                float v2 = G2s[ttl * 24 + nl];
                if (ttl <= 2) {
                    int a = 2 - ttl;
                    #pragma unroll
                    for (int oo = 0; oo < 4; oo++) {
                        int o = og * 4 + oo;
                        acc0[oo] += Hs[(a * 3 + 0) * 16 + o] * v0
                                  + Hs[(a * 3 + 1) * 16 + o] * v1
                                  + Hs[(a * 3 + 2) * 16 + o] * v2;
                    }
                }
                if (ttl >= 1) {
                    int a = 3 - ttl;
                    #pragma unroll
                    for (int oo = 0; oo < 4; oo++) {
                        int o = og * 4 + oo;
                        acc1[oo] += Hs[(a * 3 + 0) * 16 + o] * v0
                                  + Hs[(a * 3 + 1) * 16 + o] * v1
                                  + Hs[(a * 3 + 2) * 16 + o] * v2;
                    }
                }
            }
            #pragma unroll
            for (int oo = 0; oo < 4; oo++) {
                int o = og * 4 + oo;
                g_actA[(tp * 16 + o) * NN + n] = fmaxf(fmaxf(acc0[oo], acc1[oo]), 0.f);
            }
        }
    }
    // --- barrier 2 window: S3 A band (Sg/Sg2, stable since barrier 1) ---
    __syncthreads();
    if (tid == 0) bg = bar_arrive();
    loadA24(mat ? g_Sg2 : Sg, gm0, mat != 0, As);
    if (tid == 0) bar_wait(bg);
    __syncthreads();

    // ======== S3: e2 GEMMs (A band prefetched) ========
    big_stage<false>(nullptr, false, g_actA, mat ? g_G2 : g_G1, gm0, gj0, As, Bs0, Bs1);
    // --- barrier 3 window: e2 Hs + G0 (g_actA, stable since bar 2) tt=0/1 rows ---
    __syncthreads();
    if (tid == 0) bg = bar_arrive();
    {
        int tp = bid & 7;
        int src0 = (2 * tp - 2 + 16) & 15;
        int src1 = (2 * tp - 1 + 16) & 15;
        loadB16(g_actA, src0 * 16, Bs0);
        loadB16(g_actA, src1 * 16, Bs1);
        build_Hs(Hs, h_e2, sv, 16, 2, (bid >> 3) * 2);
    }
    if (tid == 0) bar_wait(bg);
    cp_wait_all();
    __syncthreads();

    // ======== S4: combine e2 -> actB ========
    combine_e2_body(g_actA, g_G1, g_G2, g_actB, bid & 7, (bid >> 3) * 2,
                    Hs, Bs0, Bs1);
    // --- barrier 4 ---
    __syncthreads();
    if (tid == 0) { bg = bar_arrive(); bar_wait(bg); }
    __syncthreads();

    // ======== S5: d1 GEMMs (A resident) ========
    big_stage<false>(nullptr, false, g_actB, mat ? g_G2 : g_G1, gm0, gj0, As, Bs0, Bs1);
    // --- barrier 5 window: d1 Hs + G0 (g_actB, stable since bar 4) tl0 rows ---
    __syncthreads();
    if (tid == 0) bg = bar_arrive();
    {
        int tau = bid & 15;
        int tl0 = tau >> 1;
        loadB16(g_actB, tl0 * 32, Bs0);
        loadB16(g_actB, tl0 * 32 + 16, Bs1);
        build_Hs(Hs, h_d1, sv, 32, 2, (bid >> 4) * 2);
    }
    if (tid == 0) bar_wait(bg);
    cp_wait_all();
    __syncthreads();

    // ======== S6: combine d1 -> actA ========
    combine_d1_body(g_actB, g_G1, g_G2, g_actA, bid & 15, (bid >> 4) * 2,
                    Hs, (bid & 15) >> 1, Bs0, Bs1);
    // --- barrier 6 ---
    __syncthreads();
    if (tid == 0) { bg = bar_arrive(); bar_wait(bg); }
    __syncthreads();

    // ======== S7: d2 GEMMs (A resident) ========
    big_stage<false>(nullptr, false, g_actA, mat ? g_G2 : g_G1, gm0, gj0, As, Bs0, Bs1);
    // --- barrier 7 window: d2 Hs + G0 (g_actA, stable since bar 6) tl0 rows ---
    __syncthreads();
    if (tid == 0) bg = bar_arrive();
    if (bid < 32) {
        int tl0 = bid >> 1;
        loadB16(g_actA, tl0 * 16, Bs0);
        for (int idx = tid; idx < 144; idx += 128) {
            int b = idx % 3, a = (idx / 3) % 3, i = idx / 9;
            Hs[idx] = fold_H(&h_d2[i * 3], sv, a, b);
        }
    }
    if (tid == 0) bar_wait(bg);
    cp_wait_all();
    __syncthreads();

    // ======== S8: final combine d2 -> out (N, T) ========
    if (bid < 32) {
        const int tau = bid;
        const int tl0 = tau >> 1;
        if (tid < 96) {
            const int n2 = 2 * tid;
            float2 acc = make_float2(0.f, 0.f);
            #pragma unroll
            for (int a = 0; a < 3; a++) {
                int src = tau - a; if (src < 0) src += TT;
                if (src & 1) continue;
                int tl = src >> 1;
                bool insm = (tl == tl0);
                #pragma unroll
                for (int i = 0; i < 16; i++) {
                    float2 v0;
                    if (insm) v0 = *(const float2*)&Bs0[i * KS + n2];
                    else      v0 = __ldcg((const float2*)&g_actA[(tl * 16 + i) * NN + n2]);
                    float2 v1 = __ldcg((const float2*)&g_G1[(tl * 16 + i) * NN + n2]);
                    float2 v2 = __ldcg((const float2*)&g_G2[(tl * 16 + i) * NN + n2]);
                    float h0 = Hs[(i * 3 + a) * 3 + 0];
                    float h1 = Hs[(i * 3 + a) * 3 + 1];
                    float h2 = Hs[(i * 3 + a) * 3 + 2];
                    acc.x += h0 * v0.x + h1 * v1.x + h2 * v2.x;
                    acc.y += h0 * v0.y + h1 * v1.y + h2 * v2.y;
                }
            }
            out[(n2    ) * TT + tau] = acc.x;
            out[(n2 + 1) * TT + tau] = acc.y;
        }
    }
}

// ---------------- launch ---------------------------------------------------------
extern "C" void kernel_launch(void* const* d_in, const int* in_sizes, int n_in,
                              void* d_out, int out_size)
{
    const float* X    = (const float*)d_in[0];
    const float* Sg   = (const float*)d_in[1];
    const float* s    = (const float*)d_in[2];
    const float* h_e1 = (const float*)d_in[3];
    const float* h_e2 = (const float*)d_in[4];
    const float* h_d1 = (const float*)d_in[5];
    const float* h_d2 = (const float*)d_in[6];
    float* out = (float*)d_out;

    mega<<<NB, 128>>>(X, Sg, s, h_e1, h_e2, h_d1, h_d2, out);
}

// round 15
// speedup vs baseline: 1.0441x; 1.0441x over previous
#include <cuda_runtime.h>
#include <cstdint>

// GTConvAE — fused persistent kernel, R15 = R13 with barrier 1 removed:
// S0 (Sg2 + P) and S1' (e1) merged into one segment; e1 waits for P via a
// release/acquire producer counter (16 P-tile blocks), which is satisfied long
// before the Sg2 blocks finish. 6 grid barriers per pass (was 7).
// Kronecker identity: S^k x[tau] = sum_{a,b<3} c_k[a][b] * Sg^b x[(tau-a) mod t].
// Layer = two GEMMs (G1=Sg@act, G2=Sg2@act) + 9-term combine with folded filters.

#define NN  192
#define TT  32
#define NB  128
#define KS  196
#define NBAR 6    // barriers per kernel pass (replay-safe bases divide by this)

// ---------------- scratch --------------------------------------------------------
__device__ float g_Sg2 [NN * NN];
__device__ float g_G1  [256 * NN];
__device__ float g_G2  [256 * NN];
__device__ float g_actA[256 * NN];
__device__ float g_actB[256 * NN];
__device__ unsigned g_cnt = 0;
__device__ unsigned g_gen = 0;
__device__ unsigned g_pf  = 0;   // P-tile producer counter (16 per pass)

// ---------------- split grid barrier ---------------------------------------------
__device__ __forceinline__ unsigned bar_arrive()
{
    unsigned gen;
    asm volatile("ld.relaxed.gpu.u32 %0, [%1];"
                 : "=r"(gen) : "l"(&g_gen) : "memory");
    unsigned prev;
    asm volatile("atom.release.gpu.add.u32 %0, [%1], %2;"
                 : "=r"(prev) : "l"(&g_cnt), "r"(1u) : "memory");
    if (prev == NB - 1) {
        asm volatile("st.relaxed.gpu.u32 [%0], %1;"
                     :: "l"(&g_cnt), "r"(0u) : "memory");
        asm volatile("st.release.gpu.u32 [%0], %1;"
                     :: "l"(&g_gen), "r"(gen + 1u) : "memory");
    }
    return gen + 1;
}
__device__ __forceinline__ void bar_wait(unsigned target)
{
    unsigned cur;
    do {
        asm volatile("ld.acquire.gpu.u32 %0, [%1];"
                     : "=r"(cur) : "l"(&g_gen) : "memory");
    } while ((int)(cur - target) < 0);
}

// ---------------- cp.async helpers ----------------------------------------------
__device__ __forceinline__ void cp16(float* dst, const float* src, bool cg)
{
    uint32_t d = (uint32_t)__cvta_generic_to_shared(dst);
    if (cg)
        asm volatile("cp.async.cg.shared.global [%0], [%1], 16;" :: "r"(d), "l"(src));
    else
        asm volatile("cp.async.ca.shared.global [%0], [%1], 16;" :: "r"(d), "l"(src));
}
__device__ __forceinline__ void cp_wait_all()
{
    asm volatile("cp.async.wait_all;" ::: "memory");
}

// ---------------- tile loaders (128 threads) -------------------------------------
__device__ __forceinline__ void loadA24(const float* __restrict__ A, int m0,
                                        bool cg, float* As)
{
    #pragma unroll
    for (int r = 0; r < 9; r++) {
        int op = threadIdx.x + 128 * r;          // 0..1151
        int ml = op / 48, kq = op - ml * 48;
        cp16(&As[ml * KS + 4 * kq], &A[(m0 + ml) * NN + 4 * kq], cg);
    }
}
__device__ __forceinline__ void loadB16(const float* __restrict__ Bg, int j0,
                                        float* Bsb)
{
    #pragma unroll
    for (int r = 0; r < 6; r++) {
        int op = threadIdx.x + 128 * r;          // 0..767
        int jl = op / 48, kq = op - jl * 48;
        cp16(&Bsb[jl * KS + 4 * kq], &Bg[(j0 + jl) * NN + 4 * kq], true);
    }
}

// ---------------- compute one 24m x 16j tile (128 threads) -----------------------
template <bool CROW>
__device__ __forceinline__ void tile_compute(const float* __restrict__ As,
                                             const float* __restrict__ Bsb,
                                             float* __restrict__ C, int m0, int j0)
{
    const int tid = threadIdx.x;
    const int tx = tid & 15, ty = tid >> 4;
    float acc0 = 0.f, acc1 = 0.f, acc2 = 0.f;
    const float* bp  = Bsb + tx * KS;
    const float* ap0 = As + ty * KS;
    const float* ap1 = ap0 + 8 * KS;
    const float* ap2 = ap0 + 16 * KS;
    #pragma unroll 8
    for (int k = 0; k < NN; k += 4) {
        float4 b  = *(const float4*)(bp + k);
        float4 a0 = *(const float4*)(ap0 + k);
        float4 a1 = *(const float4*)(ap1 + k);
        float4 a2 = *(const float4*)(ap2 + k);
        acc0 += a0.x * b.x; acc0 += a0.y * b.y; acc0 += a0.z * b.z; acc0 += a0.w * b.w;
        acc1 += a1.x * b.x; acc1 += a1.y * b.y; acc1 += a1.z * b.z; acc1 += a1.w * b.w;
        acc2 += a2.x * b.x; acc2 += a2.y * b.y; acc2 += a2.z * b.z; acc2 += a2.w * b.w;
    }
    const int j = j0 + tx;
    if (CROW) {
        C[(m0 + ty     ) * NN + j] = acc0;
        C[(m0 + ty +  8) * NN + j] = acc1;
        C[(m0 + ty + 16) * NN + j] = acc2;
    } else {
        C[j * NN + m0 + ty     ] = acc0;
        C[j * NN + m0 + ty +  8] = acc1;
        C[j * NN + m0 + ty + 16] = acc2;
    }
}

// ---------------- big GEMM stage: 2 j-tiles, double-buffered B -------------------
template <bool LOADA>
__device__ void big_stage(const float* __restrict__ A, bool acg,
                          const float* __restrict__ Bact,
                          float* __restrict__ C, int m0, int j0,
                          float* As, float* Bs0, float* Bs1)
{
    if (LOADA) loadA24(A, m0, acg, As);
    loadB16(Bact, j0, Bs0);
    cp_wait_all(); __syncthreads();
    loadB16(Bact, j0 + 16, Bs1);
    tile_compute<false>(As, Bs0, C, m0, j0);
    cp_wait_all(); __syncthreads();
    tile_compute<false>(As, Bs1, C, m0, j0 + 16);
}

// ---------------- S0 tile: B from column-slices (Sg or X) ------------------------
template <int BMODE, bool CROW>
__device__ void s0_tile(const float* __restrict__ A, const float* __restrict__ Bg,
                        int j0, float* __restrict__ C, int m0,
                        float* As, float* Bs0)
{
    loadA24(A, m0, false, As);
    const int tid = threadIdx.x;
    #pragma unroll
    for (int r = 0; r < 24; r++) {
        int idx = tid + 128 * r;                 // 0..3071
        int jl = idx & 15, kk = idx >> 4;
        Bs0[jl * KS + kk] = (BMODE == 1) ? Bg[kk * NN + j0 + jl]
                                         : Bg[kk * TT + j0 + jl];
    }
    cp_wait_all(); __syncthreads();
    tile_compute<CROW>(As, Bs0, C, m0, j0);
}

// ---------------- folded filters -------------------------------------------------
__device__ __forceinline__ float fold_H(const float* __restrict__ h3,
                                        const float sv[4], int a, int b)
{
    float c0 = (a == 0 && b == 0) ? 1.f : 0.f;
    float c1 = (a < 2 && b < 2) ? sv[a * 2 + b] : 0.f;
    float c2 = 0.f;
    #pragma unroll
    for (int a1 = 0; a1 < 2; a1++)
        #pragma unroll
        for (int b1 = 0; b1 < 2; b1++) {
            int a2 = a - a1, b2 = b - b1;
            if (a2 >= 0 && a2 < 2 && b2 >= 0 && b2 < 2)
                c2 += sv[a1 * 2 + b1] * sv[a2 * 2 + b2];
        }
    return h3[0] * c0 + h3[1] * c1 + h3[2] * c2;
}

__device__ __forceinline__ void build_Hs(float* Hs, const float* __restrict__ h,
                                         const float sv[4], int CI, int OT, int ob)
{
    for (int idx = threadIdx.x; idx < CI * 9 * OT; idx += 128) {
        int oo = idx % OT;
        int tmp = idx / OT;
        int b = tmp % 3, a = (tmp / 3) % 3, i = tmp / 9;
        Hs[idx] = fold_H(&h[((ob + oo) * CI + i) * 3], sv, a, b);
    }
}

// ---------------- encoder combine body (Hs prebuilt): float2, 96 threads ---------
template <int CI, int CO, int OT>
__device__ void combine_enc_body(const float* __restrict__ G0,
                                 const float* __restrict__ G1,
                                 const float* __restrict__ G2,
                                 float* __restrict__ out, int t, int tp, int ob,
                                 const float* Hs)
{
    const int tid = threadIdx.x;
    if (tid < 96) {
        const int n2 = 2 * tid;
        float2 acc0[OT], acc1[OT];
        #pragma unroll
        for (int o = 0; o < OT; o++) {
            acc0[o] = make_float2(0.f, 0.f); acc1[o] = make_float2(0.f, 0.f);
        }
        #pragma unroll
        for (int tt = 0; tt < 4; tt++) {
            int src = (2 * tp - 2 + tt + t) & (t - 1);
            #pragma unroll
            for (int i = 0; i < CI; i++) {
                float2 v0 = __ldcg((const float2*)&G0[(src * CI + i) * NN + n2]);
                float2 v1 = __ldcg((const float2*)&G1[(src * CI + i) * NN + n2]);
                float2 v2 = __ldcg((const float2*)&G2[(src * CI + i) * NN + n2]);
                if (tt <= 2) {
                    const float* Hp = &Hs[(i * 3 + (2 - tt)) * 3 * OT];
                    #pragma unroll
                    for (int o = 0; o < OT; o++) {
                        float h0 = Hp[o], h1 = Hp[OT + o], h2 = Hp[2 * OT + o];
                        acc0[o].x += h0 * v0.x + h1 * v1.x + h2 * v2.x;
                        acc0[o].y += h0 * v0.y + h1 * v1.y + h2 * v2.y;
                    }
                }
                if (tt >= 1) {
                    const float* Hp = &Hs[(i * 3 + (3 - tt)) * 3 * OT];
                    #pragma unroll
                    for (int o = 0; o < OT; o++) {
                        float h0 = Hp[o], h1 = Hp[OT + o], h2 = Hp[2 * OT + o];
                        acc1[o].x += h0 * v0.x + h1 * v1.x + h2 * v2.x;
                        acc1[o].y += h0 * v0.y + h1 * v1.y + h2 * v2.y;
                    }
                }
            }
        }
        #pragma unroll
        for (int o = 0; o < OT; o++) {
            float2 r;
            r.x = fmaxf(fmaxf(acc0[o].x, acc1[o].x), 0.f);
            r.y = fmaxf(fmaxf(acc0[o].y, acc1[o].y), 0.f);
            *(float2*)&out[(tp * CO + ob + o) * NN + n2] = r;
        }
    }
}

// ---------------- decoder combine body (Hs prebuilt) -----------------------------
template <int CI, int CO, int OT>
__device__ void combine_dec_body(const float* __restrict__ G0,
                                 const float* __restrict__ G1,
                                 const float* __restrict__ G2,
                                 float* __restrict__ out, int t, int tau, int ob,
                                 const float* Hs)
{
    const int tid = threadIdx.x;
    if (tid < 96) {
        const int n2 = 2 * tid;
        float2 acc[OT];
        #pragma unroll
        for (int o = 0; o < OT; o++) acc[o] = make_float2(0.f, 0.f);
        #pragma unroll
        for (int a = 0; a < 3; a++) {
            int src = tau - a; if (src < 0) src += t;
            if (src & 1) continue;             // zero-stuffed upsample
            int tl = src >> 1;
            #pragma unroll 16
            for (int i = 0; i < CI; i++) {
                float2 v0 = __ldcg((const float2*)&G0[(tl * CI + i) * NN + n2]);
                float2 v1 = __ldcg((const float2*)&G1[(tl * CI + i) * NN + n2]);
                float2 v2 = __ldcg((const float2*)&G2[(tl * CI + i) * NN + n2]);
                const float* Hp = &Hs[(i * 3 + a) * 3 * OT];
                #pragma unroll
                for (int o = 0; o < OT; o++) {
                    float h0 = Hp[o], h1 = Hp[OT + o], h2 = Hp[2 * OT + o];
                    acc[o].x += h0 * v0.x + h1 * v1.x + h2 * v2.x;
                    acc[o].y += h0 * v0.y + h1 * v1.y + h2 * v2.y;
                }
            }
        }
        #pragma unroll
        for (int o = 0; o < OT; o++) {
            float2 r;
            r.x = fmaxf(acc[o].x, 0.f);
            r.y = fmaxf(acc[o].y, 0.f);
            *(float2*)&out[(tau * CO + ob + o) * NN + n2] = r;
        }
    }
}

// ---------------- persistent mega-kernel ----------------------------------------
__global__ __launch_bounds__(128, 1) void mega(
    const float* __restrict__ X,    const float* __restrict__ Sg,
    const float* __restrict__ s,    const float* __restrict__ h_e1,
    const float* __restrict__ h_e2, const float* __restrict__ h_d1,
    const float* __restrict__ h_d2, float* __restrict__ out)
{
    __shared__ float As[24 * KS];    // persistent A band
    __shared__ float Bs0[16 * KS];
    __shared__ float Bs1[16 * KS];
    __shared__ float Hs[576];
    __shared__ float G2s[96];

    const int bid = blockIdx.x;
    const int tid = threadIdx.x;

    const int mat = bid >> 6;                 // 0: Sg, 1: Sg2
    const int sub = bid & 63;
    const int gm0 = (sub >> 3) * 24;
    const int gj0 = (sub & 7) * 32;

    const float sv[4] = { s[0], s[1], s[2], s[3] };
    unsigned bg = 0;

    unsigned basegen;
    asm volatile("ld.relaxed.gpu.u32 %0, [%1];" : "=r"(basegen) : "l"(&g_gen));
    const unsigned ptarget = (basegen / NBAR) * 16u + 16u;   // P counter target

    // ======== S0 (merged with S1'): Sg2 (96 tiles) + P (16 tiles) ========
    if (bid < 96) {
        int mb = bid / 12, jt = bid % 12;
        s0_tile<1, true>(Sg, Sg, jt * 16, g_Sg2, mb * 24, As, Bs0);
    } else if (bid < 112) {
        int b2 = bid - 96;
        int mb = b2 >> 1, jt = b2 & 1;
        s0_tile<2, false>(Sg, X, jt * 16, g_G1, mb * 24, As, Bs0);
        // publish P tile (all threads' stores ordered by syncthreads, then release)
        __syncthreads();
        if (tid == 0) {
            unsigned dummy;
            asm volatile("atom.release.gpu.add.u32 %0, [%1], %2;"
                         : "=r"(dummy) : "l"(&g_pf), "r"(1u) : "memory");
        }
    }
    __syncthreads();   // As/Bs0 reuse below

    // ======== S1': e1 combine with fused mini-GEMM for G2 (P via flag) ========
    {
        const int tp = bid & 15, nb = bid >> 4;
        const int n0 = nb * 24;
        loadA24(Sg, n0, false, As);           // Sg rows n0..n0+23 (input)
        for (int idx = tid; idx < 144; idx += 128) {   // CI=1, OT=16 table
            int o = idx & 15, ab = idx >> 4;
            Hs[idx] = fold_H(&h_e1[o * 3], sv, ab / 3, ab % 3);
        }
        // wait for all 16 P tiles (ready early: P is ~1/6 of an Sg2 tile)
        if (tid == 0) {
            unsigned v;
            do {
                asm volatile("ld.acquire.gpu.u32 %0, [%1];"
                             : "=r"(v) : "l"(&g_pf) : "memory");
            } while ((int)(v - ptarget) < 0);
        }
        __syncthreads();
        #pragma unroll
        for (int r = 0; r < 2; r++) {         // P rows for 4 source taus
            int op = tid + 128 * r;
            if (op < 192) {
                int ttl = op / 48, kq = op - ttl * 48;
                int src = (2 * tp - 2 + ttl + TT) & (TT - 1);
                cp16(&Bs0[ttl * KS + 4 * kq], &g_G1[src * NN + 4 * kq], true);
            }
        }
        cp_wait_all(); __syncthreads();
        if (tid < 96) {                       // mini-GEMM: 24 n x 4 src
            int nl = tid % 24, st = tid / 24;
            float acc = 0.f;
            const float* ap = As + nl * KS;
            const float* bp = Bs0 + st * KS;
            #pragma unroll 12
            for (int k = 0; k < NN; k += 4) {
                float4 a = *(const float4*)(ap + k);
                float4 b = *(const float4*)(bp + k);
                acc += a.x * b.x; acc += a.y * b.y; acc += a.z * b.z; acc += a.w * b.w;
            }
            G2s[st * 24 + nl] = acc;
        }
        __syncthreads();
        if (tid < 96) {                       // combine: 24 n x 4 o-groups of 4
            int nl = tid % 24, og = tid / 24;
            int n = n0 + nl;
            float acc0[4] = {0.f, 0.f, 0.f, 0.f};
            float acc1[4] = {0.f, 0.f, 0.f, 0.f};
            #pragma unroll
            for (int ttl = 0; ttl < 4; ttl++) {
                int src = (2 * tp - 2 + ttl + TT) & (TT - 1);
                float v0 = X[n * TT + src];
                float v1 = Bs0[ttl * KS + n];
                float v2 = G2s[ttl * 24 + nl];
                if (ttl <= 2) {
                    int a = 2 - ttl;
                    #pragma unroll
                    for (int oo = 0; oo < 4; oo++) {
                        int o = og * 4 + oo;
                        acc0[oo] += Hs[(a * 3 + 0) * 16 + o] * v0
                                  + Hs[(a * 3 + 1) * 16 + o] * v1
                                  + Hs[(a * 3 + 2) * 16 + o] * v2;
                    }
                }
                if (ttl >= 1) {
                    int a = 3 - ttl;
                    #pragma unroll
                    for (int oo = 0; oo < 4; oo++) {
                        int o = og * 4 + oo;
                        acc1[oo] += Hs[(a * 3 + 0) * 16 + o] * v0
                                  + Hs[(a * 3 + 1) * 16 + o] * v1
                                  + Hs[(a * 3 + 2) * 16 + o] * v2;
                    }
                }
            }
            #pragma unroll
            for (int oo = 0; oo < 4; oo++) {
                int o = og * 4 + oo;
                g_actA[(tp * 16 + o) * NN + n] = fmaxf(fmaxf(acc0[oo], acc1[oo]), 0.f);
            }
        }
    }
    // --- barrier 1 window: mat0 prefetch Sg A band (input — always legal).
    //     mat1 loads Sg2 A band inside S3 (Sg2 only guaranteed after release). ---
    __syncthreads();
    if (tid == 0) bg = bar_arrive();
    if (mat == 0) loadA24(Sg, gm0, false, As);
    if (tid == 0) bar_wait(bg);
    __syncthreads();

    // ======== S3: e2 GEMMs ========
    if (mat == 0)
        big_stage<false>(nullptr, false, g_actA, g_G1, gm0, gj0, As, Bs0, Bs1);
    else
        big_stage<true>(g_Sg2, true, g_actA, g_G2, gm0, gj0, As, Bs0, Bs1);
    // --- barrier 2 window: e2 combine Hs ---
    __syncthreads();
    if (tid == 0) bg = bar_arrive();
    build_Hs(Hs, h_e2, sv, 16, 2, (bid >> 3) * 2);
    if (tid == 0) bar_wait(bg);
    __syncthreads();

    // ======== S4: combine e2 -> actB ========
    combine_enc_body<16, 32, 2>(g_actA, g_G1, g_G2, g_actB, 16,
                                bid & 7, (bid >> 3) * 2, Hs);
    // --- barrier 3 ---
    __syncthreads();
    if (tid == 0) { bg = bar_arrive(); bar_wait(bg); }
    __syncthreads();

    // ======== S5: d1 GEMMs (A resident) ========
    big_stage<false>(nullptr, false, g_actB, mat ? g_G2 : g_G1, gm0, gj0, As, Bs0, Bs1);
    // --- barrier 4 window: d1 combine Hs ---
    __syncthreads();
    if (tid == 0) bg = bar_arrive();
    build_Hs(Hs, h_d1, sv, 32, 2, (bid >> 4) * 2);
    if (tid == 0) bar_wait(bg);
    __syncthreads();

    // ======== S6: combine d1 -> actA ========
    combine_dec_body<32, 16, 2>(g_actB, g_G1, g_G2, g_actA, 16,
                                bid & 15, (bid >> 4) * 2, Hs);
    // --- barrier 5 ---
    __syncthreads();
    if (tid == 0) { bg = bar_arrive(); bar_wait(bg); }
    __syncthreads();

    // ======== S7: d2 GEMMs (A resident) ========
    big_stage<false>(nullptr, false, g_actA, mat ? g_G2 : g_G1, gm0, gj0, As, Bs0, Bs1);
    // --- barrier 6 window: d2 Hs (blocks < 32) ---
    __syncthreads();
    if (tid == 0) bg = bar_arrive();
    if (bid < 32) {
        for (int idx = tid; idx < 144; idx += 128) {   // CI=16, OT=1
            int b = idx % 3, a = (idx / 3) % 3, i = idx / 9;
            Hs[idx] = fold_H(&h_d2[i * 3], sv, a, b);
        }
    }
    if (tid == 0) bar_wait(bg);
    __syncthreads();

    // ======== S8: final combine d2 -> out (N, T) ========
    if (bid < 32) {
        const int tau = bid;
        if (tid < 96) {
            const int n2 = 2 * tid;
            float2 acc = make_float2(0.f, 0.f);
            #pragma unroll
            for (int a = 0; a < 3; a++) {
                int src = tau - a; if (src < 0) src += TT;
                if (src & 1) continue;
                int tl = src >> 1;
                #pragma unroll
                for (int i = 0; i < 16; i++) {
                    float2 v0 = __ldcg((const float2*)&g_actA[(tl * 16 + i) * NN + n2]);
                    float2 v1 = __ldcg((const float2*)&g_G1[(tl * 16 + i) * NN + n2]);
                    float2 v2 = __ldcg((const float2*)&g_G2[(tl * 16 + i) * NN + n2]);
                    float h0 = Hs[(i * 3 + a) * 3 + 0];
                    float h1 = Hs[(i * 3 + a) * 3 + 1];
                    float h2 = Hs[(i * 3 + a) * 3 + 2];
                    acc.x += h0 * v0.x + h1 * v1.x + h2 * v2.x;
                    acc.y += h0 * v0.y + h1 * v1.y + h2 * v2.y;
                }
            }
            out[(n2    ) * TT + tau] = acc.x;
            out[(n2 + 1) * TT + tau] = acc.y;
        }
    }
}

// ---------------- launch ---------------------------------------------------------
extern "C" void kernel_launch(void* const* d_in, const int* in_sizes, int n_in,
                              void* d_out, int out_size)
{
    const float* X    = (const float*)d_in[0];
    const float* Sg   = (const float*)d_in[1];
    const float* s    = (const float*)d_in[2];
    const float* h_e1 = (const float*)d_in[3];
    const float* h_e2 = (const float*)d_in[4];
    const float* h_d1 = (const float*)d_in[5];
    const float* h_d2 = (const float*)d_in[6];
    float* out = (float*)d_out;

    mega<<<NB, 128>>>(X, Sg, s, h_e1, h_e2, h_d1, h_d2, out);
}